// round 8
// baseline (speedup 1.0000x reference)
#include <cuda_runtime.h>
#include <cstdint>

// WinCorr: corr[b,off,z,y,x] = (1/8) * sum_c x[b,c,z,y,x] * y[b,c,z+dz-1,y+dy-1,x+dx-1]
// x,y = (2,64,80,80,80) f32 ; out = (2,27,80,80,80) f32
// R8: dz-split (thread owns 9 offsets), 16B-aligned bulk staging + separate 1-col left halo,
//     left neighbor via shfl_up.

#define B_  2
#define C_  64
#define D_  80
#define H_  80
#define W_  80

#define TZ  4
#define TY  8
#define TXB 16           // x extent per block
#define TX  4            // x outputs per thread
#define NTH 384          // 4(tx)*8(ty)*4(tz) * 3(td)

#define SMZ 6
#define SMY 10
#define SMX 48           // row stride (floats); 16 mod 32 -> conflict-free LDS.128 phases
#define STAGES 3
#define BUFBYTES (SMZ*SMY*SMX*4)   // 11520
#define HSBYTES  (64*4)            // 256 (6*10 used, padded)
#define NROWS (SMZ*SMY)            // 60
#define NSLOTS (NROWS*6)           // 360: 5x16B chunks + 1 halo col per row

typedef unsigned long long u64;

__device__ __forceinline__ uint32_t smem_u32(const void* p) {
    return (uint32_t)__cvta_generic_to_shared(p);
}
__device__ __forceinline__ void cp_async16(uint32_t saddr, const void* gaddr, uint32_t srcsz) {
    asm volatile("cp.async.cg.shared.global [%0], [%1], 16, %2;\n"
                 :: "r"(saddr), "l"(gaddr), "r"(srcsz) : "memory");
}
__device__ __forceinline__ void cp_async4(uint32_t saddr, const void* gaddr, uint32_t srcsz) {
    asm volatile("cp.async.ca.shared.global [%0], [%1], 4, %2;\n"
                 :: "r"(saddr), "l"(gaddr), "r"(srcsz) : "memory");
}
__device__ __forceinline__ void cp_commit() {
    asm volatile("cp.async.commit_group;\n" ::: "memory");
}
template<int N> __device__ __forceinline__ void cp_wait() {
    asm volatile("cp.async.wait_group %0;\n" :: "n"(N) : "memory");
}
__device__ __forceinline__ void ffma2(u64& acc, u64 a, u64 b) {
    asm("fma.rn.f32x2 %0, %1, %2, %0;" : "+l"(acc) : "l"(a), "l"(b));
}
__device__ __forceinline__ u64 packf2(float lo, float hi) {
    u64 r; asm("mov.b64 %0, {%1, %2};" : "=l"(r) : "f"(lo), "f"(hi)); return r;
}
__device__ __forceinline__ float2 unpackf2(u64 v) {
    float2 r; asm("mov.b64 {%0, %1}, %2;" : "=f"(r.x), "=f"(r.y) : "l"(v)); return r;
}

__global__ void __launch_bounds__(NTH, 2)
wincorr_kernel(const float* __restrict__ x,
               const float* __restrict__ y,
               float* __restrict__ out)
{
    // ---- decode block -> (b, z0, y0, x0) ----
    int bid = blockIdx.x;
    int bx = bid % (W_ / TXB); bid /= (W_ / TXB);   // 5
    int by = bid % (H_ / TY);  bid /= (H_ / TY);    // 10
    int bz = bid % (D_ / TZ);  bid /= (D_ / TZ);    // 20
    int b  = bid;
    const int z0 = bz * TZ, y0 = by * TY, x0 = bx * TXB;

    const int tid = threadIdx.x;
    const int tx = tid & 3;
    const int ty = (tid >> 2) & 7;
    const int tz = (tid >> 5) & 3;
    const int td = tid >> 7;         // dz slice 0..2

    // sm col j holds gmem column x0 + j (j = 0..19 staged; stride 48)
    __shared__ __align__(16) float sm[STAGES][SMZ][SMY][SMX];
    __shared__ __align__(16) float hs[STAGES][64];   // left halo col (gmem x0-1), idx lz*10+ly

    const int plane = H_ * W_;       // 6400
    const int vol   = D_ * plane;    // 512000
    const uint32_t volbytes = (uint32_t)vol * 4u;

    const float* xb = x + (size_t)b * C_ * vol;
    const float* yb = y + (size_t)b * C_ * vol;
    const char*  ybc = (const char*)yb;

    // ---- one staging slot per thread (360 active of 384) ----
    const bool active = tid < NSLOTS;
    uint32_t sadr = 0, goff = 0, csz = 0, sstep = 0;
    bool is16 = true;
    {
        int slot = active ? tid : 0;
        int r = slot / 6;
        int k = slot - r * 6;            // 0..4 = 16B chunk, 5 = halo col
        int lz = r / SMY;
        int ly = r - lz * SMY;
        int gz = z0 - 1 + lz, gy = y0 - 1 + ly;
        bool rowok = ((unsigned)gz < (unsigned)D_) && ((unsigned)gy < (unsigned)H_);
        int cz = min(max(gz, 0), D_ - 1);
        int cy = min(max(gy, 0), H_ - 1);
        int rowbase = cz * plane + cy * W_;
        is16 = (k < 5);
        if (is16) {
            int cx = x0 + 4 * k;                       // 16B-aligned in gmem
            bool ok = rowok && (cx < W_);              // cx+4 <= W when cx < W here
            goff = (uint32_t)((rowbase + min(cx, W_ - 4)) * 4);
            csz  = ok ? 16u : 0u;
            sadr = smem_u32(&sm[0][lz][ly][4 * k]);
            sstep = BUFBYTES;
        } else {
            int hx = x0 - 1;
            bool ok = rowok && (hx >= 0);
            goff = (uint32_t)((rowbase + max(hx, 0)) * 4);
            csz  = ok ? 4u : 0u;
            sadr = smem_u32(&hs[0][lz * SMY + ly]);
            sstep = HSBYTES;
        }
        if (!active) csz = 0;
    }

    // 9 offsets (dz = td), 4 x-outputs -> 18 u64 accumulators
    u64 acc01[9], acc23[9];
#pragma unroll
    for (int o = 0; o < 9; o++) { acc01[o] = 0ull; acc23[o] = 0ull; }

    const float* xp = xb + (size_t)(z0 + tz) * plane + (y0 + ty) * W_ + x0 + tx * TX;
    const int zp = tz + td;          // smem z-plane this thread reads
    const int hbase = zp * SMY + ty; // halo index base

    // ---- prologue: stage channels 0 and 1 ----
#pragma unroll
    for (int s = 0; s < STAGES - 1; s++) {
        const uint32_t cb = (uint32_t)s * volbytes;
        const uint32_t bo = (uint32_t)s * sstep;
        if (active) {
            if (is16) cp_async16(sadr + bo, ybc + (goff + cb), csz);
            else      cp_async4 (sadr + bo, ybc + (goff + cb), csz);
        }
        cp_commit();
    }

    float4 xv = *(const float4*)xp;

    for (int c = 0; c < C_; c++) {
        if (c == C_ - 1) cp_wait<0>(); else cp_wait<1>();
        __syncthreads();

        // issue stage c+2 into buffer (c+2)%3
        if (c + 2 < C_) {
            const uint32_t cb = (uint32_t)(c + 2) * volbytes;
            const uint32_t bo = (uint32_t)((c + 2) % STAGES) * sstep;
            if (active) {
                if (is16) cp_async16(sadr + bo, ybc + (goff + cb), csz);
                else      cp_async4 (sadr + bo, ybc + (goff + cb), csz);
            }
            cp_commit();
        }

        // prefetch x for c+1
        float4 xnext;
        if (c + 1 < C_) xnext = *(const float4*)(xp + (size_t)(c + 1) * vol);

        const u64 xa01 = packf2(xv.x, xv.y);
        const u64 xa23 = packf2(xv.z, xv.w);
        const float (*smb)[SMY][SMX] = sm[c % STAGES];
        const float* hsb = hs[c % STAGES];

#pragma unroll
        for (int dy = 0; dy < 3; dy++) {
            const float* row = &smb[zp][ty + dy][tx * TX];
            const ulonglong2 q = *(const ulonglong2*)row;   // gmem rel cols 0..3 (LDS.128)
            const u64 t64 = *(const u64*)(row + 4);         // rel cols 4,5      (LDS.64)
            const float hv = hsb[hbase + dy];               // rel col -1 of tx=0 (LDS.32 bcast)
            const float2 f01 = unpackf2(q.x);
            const float2 f23 = unpackf2(q.y);
            const float2 f45 = unpackf2(t64);
            const float ln = __shfl_up_sync(0xffffffffu, f23.y, 1);  // neighbor's rel col 3
            const float m1 = (tx == 0) ? hv : ln;           // this thread's rel col -1
            const u64 pm10 = packf2(m1, f01.x);
            const u64 p12  = packf2(f01.y, f23.x);
            const u64 p34  = packf2(f23.y, f45.x);
            const int a = dy * 3;
            ffma2(acc01[a + 0], xa01, pm10);
            ffma2(acc01[a + 1], xa01, q.x);
            ffma2(acc01[a + 2], xa01, p12);
            ffma2(acc23[a + 0], xa23, p12);
            ffma2(acc23[a + 1], xa23, q.y);
            ffma2(acc23[a + 2], xa23, p34);
        }

        if (c + 1 < C_) xv = xnext;
    }

    // ---- epilogue: scale + streaming stores (off = td*9 + dy*3 + dx) ----
    const float scale = 0.125f;
    const size_t sp = (size_t)(z0 + tz) * plane + (size_t)(y0 + ty) * W_ + (x0 + tx * TX);
    float* outb = out + ((size_t)b * 27 + td * 9) * vol + sp;
#pragma unroll
    for (int k = 0; k < 9; k++) {
        float2 a  = unpackf2(acc01[k]);
        float2 bq = unpackf2(acc23[k]);
        float4 o;
        o.x = a.x * scale;
        o.y = a.y * scale;
        o.z = bq.x * scale;
        o.w = bq.y * scale;
        __stcs((float4*)(outb + (size_t)k * vol), o);
    }
}

extern "C" void kernel_launch(void* const* d_in, const int* in_sizes, int n_in,
                              void* d_out, int out_size)
{
    const float* x = (const float*)d_in[0];
    const float* y = (const float*)d_in[1];
    float* out = (float*)d_out;

    const int nblocks = B_ * (D_ / TZ) * (H_ / TY) * (W_ / TXB); // 2000
    wincorr_kernel<<<nblocks, NTH>>>(x, y, out);
}

// round 9
// speedup vs baseline: 1.1954x; 1.1954x over previous
#include <cuda_runtime.h>
#include <cstdint>

// WinCorr: corr[b,off,z,y,x] = (1/8) * sum_c x[b,c,z,y,x] * y[b,c,z+dz-1,y+dy-1,x+dx-1]
// x,y = (2,64,80,80,80) f32 ; out = (2,27,80,80,80) f32
// R9: dz-split threads (9 offsets each, TX=4); 16B-aligned bulk staging + halo col;
//     left neighbor via LDS.32 (no shfl); 2 channels per buffer -> 32 barriers.

#define B_  2
#define C_  64
#define D_  80
#define H_  80
#define W_  80

#define TZ  4
#define TY  8
#define TXB 16
#define TX  4
#define NTH 384          // 4(tx)*8(ty)*4(tz) * 3(td)

#define SMZ 6
#define SMY 10
#define SMX 48           // row stride (floats)
#define CHB 2            // channels per buffer
#define NBUF 3
#define NIT (C_/CHB)     // 32

#define CHSTEP (SMZ*SMY*SMX*4)       // 11520 bytes per channel tile
#define BUFB   (CHB*CHSTEP)          // 23040 per buffer
#define HCH    256                   // halo bytes per channel (64 floats)
#define HB     (CHB*HCH)             // 512 per buffer
#define NROWS (SMZ*SMY)              // 60
#define NSLOTS (NROWS*6)             // 360: 5x16B chunks + 1 halo col per row

typedef unsigned long long u64;

__device__ __forceinline__ uint32_t smem_u32(const void* p) {
    return (uint32_t)__cvta_generic_to_shared(p);
}
__device__ __forceinline__ void cp_async16(uint32_t saddr, const void* gaddr, uint32_t srcsz) {
    asm volatile("cp.async.cg.shared.global [%0], [%1], 16, %2;\n"
                 :: "r"(saddr), "l"(gaddr), "r"(srcsz) : "memory");
}
__device__ __forceinline__ void cp_async4(uint32_t saddr, const void* gaddr, uint32_t srcsz) {
    asm volatile("cp.async.ca.shared.global [%0], [%1], 4, %2;\n"
                 :: "r"(saddr), "l"(gaddr), "r"(srcsz) : "memory");
}
__device__ __forceinline__ void cp_commit() {
    asm volatile("cp.async.commit_group;\n" ::: "memory");
}
template<int N> __device__ __forceinline__ void cp_wait() {
    asm volatile("cp.async.wait_group %0;\n" :: "n"(N) : "memory");
}
__device__ __forceinline__ void ffma2(u64& acc, u64 a, u64 b) {
    asm("fma.rn.f32x2 %0, %1, %2, %0;" : "+l"(acc) : "l"(a), "l"(b));
}
__device__ __forceinline__ u64 packf2(float lo, float hi) {
    u64 r; asm("mov.b64 %0, {%1, %2};" : "=l"(r) : "f"(lo), "f"(hi)); return r;
}
__device__ __forceinline__ float2 unpackf2(u64 v) {
    float2 r; asm("mov.b64 {%0, %1}, %2;" : "=f"(r.x), "=f"(r.y) : "l"(v)); return r;
}

__global__ void __launch_bounds__(NTH, 2)
wincorr_kernel(const float* __restrict__ x,
               const float* __restrict__ y,
               float* __restrict__ out)
{
    // ---- decode block -> (b, z0, y0, x0) ----
    int bid = blockIdx.x;
    int bx = bid % (W_ / TXB); bid /= (W_ / TXB);   // 5
    int by = bid % (H_ / TY);  bid /= (H_ / TY);    // 10
    int bz = bid % (D_ / TZ);  bid /= (D_ / TZ);    // 20
    int b  = bid;
    const int z0 = bz * TZ, y0 = by * TY, x0 = bx * TXB;

    const int tid = threadIdx.x;
    const int tx = tid & 3;
    const int ty = (tid >> 2) & 7;
    const int tz = (tid >> 5) & 3;
    const int td = tid >> 7;         // dz slice 0..2

    // sm[buf][ch] col j holds gmem column x0+j (j=0..19 staged; stride 48)
    __shared__ __align__(16) float sm[NBUF][CHB][SMZ][SMY][SMX];
    __shared__ __align__(16) float hs[NBUF][CHB][64];   // left halo col (x0-1), idx lz*10+ly

    const int plane = H_ * W_;       // 6400
    const int vol   = D_ * plane;    // 512000
    const uint32_t volbytes = (uint32_t)vol * 4u;

    const float* xb = x + (size_t)b * C_ * vol;
    const float* yb = y + (size_t)b * C_ * vol;
    const char*  ybc = (const char*)yb;

    // ---- one staging slot per thread (360 active of 384) ----
    const bool active = tid < NSLOTS;
    uint32_t sadr = 0, goff = 0, csz = 0;
    bool is16 = true;
    {
        int slot = active ? tid : 0;
        int r = slot / 6;
        int k = slot - r * 6;            // 0..4 = 16B chunk, 5 = halo col
        int lz = r / SMY;
        int ly = r - lz * SMY;
        int gz = z0 - 1 + lz, gy = y0 - 1 + ly;
        bool rowok = ((unsigned)gz < (unsigned)D_) && ((unsigned)gy < (unsigned)H_);
        int cz = min(max(gz, 0), D_ - 1);
        int cy = min(max(gy, 0), H_ - 1);
        int rowbase = cz * plane + cy * W_;
        is16 = (k < 5);
        if (is16) {
            int cx = x0 + 4 * k;                       // 16B-aligned in gmem
            bool ok = rowok && (cx < W_);
            goff = (uint32_t)((rowbase + min(cx, W_ - 4)) * 4);
            csz  = ok ? 16u : 0u;
            sadr = smem_u32(&sm[0][0][lz][ly][4 * k]);
        } else {
            int hx = x0 - 1;
            bool ok = rowok && (hx >= 0);
            goff = (uint32_t)((rowbase + max(hx, 0)) * 4);
            csz  = ok ? 4u : 0u;
            sadr = smem_u32(&hs[0][0][lz * SMY + ly]);
        }
        if (!active) csz = 0;
    }
    const uint32_t bstep = is16 ? (uint32_t)BUFB : (uint32_t)HB;
    const uint32_t cstep = is16 ? (uint32_t)CHSTEP : (uint32_t)HCH;

    // 9 offsets (dz = td), 4 x-outputs -> 18 u64 accumulators
    u64 acc01[9], acc23[9];
#pragma unroll
    for (int o = 0; o < 9; o++) { acc01[o] = 0ull; acc23[o] = 0ull; }

    const float* xp = xb + (size_t)(z0 + tz) * plane + (y0 + ty) * W_ + x0 + tx * TX;
    const int zp = tz + td;          // smem z-plane this thread reads
    const int hbase = zp * SMY + ty;

    // ---- prologue: stage buffers 0,1 (channels 0..3) ----
#pragma unroll
    for (int s = 0; s < NBUF - 1; s++) {
#pragma unroll
        for (int ch = 0; ch < CHB; ch++) {
            const uint32_t cb = (uint32_t)(s * CHB + ch) * volbytes;
            const uint32_t sa = sadr + (uint32_t)s * bstep + (uint32_t)ch * cstep;
            if (active) {
                if (is16) cp_async16(sa, ybc + (goff + cb), csz);
                else      cp_async4 (sa, ybc + (goff + cb), csz);
            }
        }
        cp_commit();
    }

    float4 xv = *(const float4*)xp;      // x for channel 0

    for (int ib = 0; ib < NIT; ib++) {
        if (ib == NIT - 1) cp_wait<0>(); else cp_wait<1>();
        __syncthreads();

        // issue buffer ib+2 (channels 2ib+4, 2ib+5)
        if (ib + 2 < NIT) {
            const int bu = (ib + 2) % NBUF;
#pragma unroll
            for (int ch = 0; ch < CHB; ch++) {
                const uint32_t cb = (uint32_t)((ib + 2) * CHB + ch) * volbytes;
                const uint32_t sa = sadr + (uint32_t)bu * bstep + (uint32_t)ch * cstep;
                if (active) {
                    if (is16) cp_async16(sa, ybc + (goff + cb), csz);
                    else      cp_async4 (sa, ybc + (goff + cb), csz);
                }
            }
            cp_commit();
        }

        const int c0 = ib * CHB;
        const int bu = ib % NBUF;

        // x for channel c0+1, issued before the first compute block (latency covered)
        float4 xn = *(const float4*)(xp + (size_t)(c0 + 1) * vol);

#pragma unroll
        for (int ch = 0; ch < CHB; ch++) {
            const float4 xc = (ch == 0) ? xv : xn;
            const u64 xa01 = packf2(xc.x, xc.y);
            const u64 xa23 = packf2(xc.z, xc.w);
            const float (*smb)[SMY][SMX] = sm[bu][ch];
            const float* hsb = hs[bu][ch];

#pragma unroll
            for (int dy = 0; dy < 3; dy++) {
                const float* row = &smb[zp][ty + dy][tx * TX];
                const ulonglong2 q = *(const ulonglong2*)row;   // cols 4tx..4tx+3 (LDS.128)
                const u64 t64 = *(const u64*)(row + 4);         // cols 4tx+4,4tx+5 (LDS.64)
                // left neighbor col 4tx-1: smem scalar (tx>0) or halo array (tx==0)
                const float* mp = (tx == 0) ? &hsb[hbase + dy] : (row - 1);
                const float m1 = *mp;                           // LDS.32
                const float2 f01 = unpackf2(q.x);
                const float2 f23 = unpackf2(q.y);
                const float2 f45 = unpackf2(t64);
                const u64 pm10 = packf2(m1, f01.x);
                const u64 p12  = packf2(f01.y, f23.x);
                const u64 p34  = packf2(f23.y, f45.x);
                const int a = dy * 3;
                ffma2(acc01[a + 0], xa01, pm10);
                ffma2(acc01[a + 1], xa01, q.x);
                ffma2(acc01[a + 2], xa01, p12);
                ffma2(acc23[a + 0], xa23, p12);
                ffma2(acc23[a + 1], xa23, q.y);
                ffma2(acc23[a + 2], xa23, p34);
            }

            // after finishing ch0's FMAs, prefetch x for next iteration's ch0
            if (ch == 0 && c0 + 2 < C_)
                xv = *(const float4*)(xp + (size_t)(c0 + 2) * vol);
        }
    }

    // ---- epilogue: scale + streaming stores (off = td*9 + dy*3 + dx) ----
    const float scale = 0.125f;
    const size_t sp = (size_t)(z0 + tz) * plane + (size_t)(y0 + ty) * W_ + (x0 + tx * TX);
    float* outb = out + ((size_t)b * 27 + td * 9) * vol + sp;
#pragma unroll
    for (int k = 0; k < 9; k++) {
        float2 a  = unpackf2(acc01[k]);
        float2 bq = unpackf2(acc23[k]);
        float4 o;
        o.x = a.x * scale;
        o.y = a.y * scale;
        o.z = bq.x * scale;
        o.w = bq.y * scale;
        __stcs((float4*)(outb + (size_t)k * vol), o);
    }
}

extern "C" void kernel_launch(void* const* d_in, const int* in_sizes, int n_in,
                              void* d_out, int out_size)
{
    const float* x = (const float*)d_in[0];
    const float* y = (const float*)d_in[1];
    float* out = (float*)d_out;

    const int nblocks = B_ * (D_ / TZ) * (H_ / TY) * (W_ / TXB); // 2000
    wincorr_kernel<<<nblocks, NTH>>>(x, y, out);
}